// round 15
// baseline (speedup 1.0000x reference)
#include <cuda_runtime.h>
#include <cuda_bf16.h>

// PEPS 6x6, D=4, phys=2, batch=1024.
// Half-split at the row2|row3 bond cut: blocks 0..1023 = tops (rows 0,1,2 down),
// blocks 1024..2047 = bottoms (rows 5,4,3 up, u/d strides swapped).
// amp = dot(V_top, V_bot) over the 4096 cut states. TOPS-FIRST ordering means
// bottoms never co-reside with their producer -> spin ~ 0 (R9's loss mode).
// 2048 uniform halves / 296 lanes = 6.92 -> 3.5 config-units makespan vs 4.0.
// Flags self-reset (bottom clears after consuming) -> graph-replay safe.
// Interior engine: R11 swizzled fma.rn.f32x2 m4n8 blocking, 2 CTAs/SM.

#define NT 512

typedef unsigned long long u64;

__device__ float    g_vtop[1024 * 4096];
__device__ unsigned g_flag[1024];          // zero-init; invariant restored per run

__device__ __forceinline__ u64 pk(float v) {
    u64 r;
    asm("mov.b64 %0, {%1, %1};" : "=l"(r) : "f"(v));
    return r;
}
__device__ __forceinline__ void fma2(u64& d, u64 a, u64 b) {
    asm("fma.rn.f32x2 %0, %1, %2, %0;" : "+l"(d) : "l"(a), "l"(b));
}
__device__ __forceinline__ float2 upk(u64 v) {
    float2 r;
    asm("mov.b64 {%0, %1}, %2;" : "=f"(r.x), "=f"(r.y) : "l"(v));
    return r;
}

// Boundary-row step, all shape parameters compile-time.
template <int F, int K, int N, int PU, int UD, int SRIN>
__device__ __forceinline__ void step_b(
    float* __restrict__ W, const float* __restrict__ A, int tid)
{
    constexpr int TOTAL = N * F;
    constexpr int NOUT = (TOTAL + NT - 1) / NT;
    float accl[NOUT];
    int cnt = 0;
    for (int o = tid; o < TOTAL; o += NT) {
        const int n = o / F;
        const int m = o - n * F;
        const int dp = m / PU;
        const int ur = m - dp * PU;
        const int inb = dp * UD * PU + ur;
        float s = 0.f;
#pragma unroll
        for (int k = 0; k < K; ++k) {
            const int rin = k / UD;
            const int u = k - rin * UD;
            s = fmaf(W[inb + rin * SRIN + u * PU], A[k * N + n], s);
        }
        accl[cnt++] = s;
    }
    __syncthreads();
    cnt = 0;
    for (int o = tid; o < TOTAL; o += NT) {
        const int n = o / F;
        const int m = o - n * F;
        W[n * F + m] = accl[cnt++];
    }
    __syncthreads();
}

// Interior steps 0..4: F=1024, N=16, Pu = 1<<PSH >= 4. XOR bank swizzles:
//   1: idx ^ (((idx>>6)&3)<<4)    2: idx ^ (((idx>>5)&3)<<2)
template <int K, int PSH, int SWZI, int SWZO>
__device__ __forceinline__ void step_fast_vec(
    float* __restrict__ W, const float* __restrict__ A, int tid)
{
    const int g = tid >> 8;           // n-group: n = 8g..8g+7
    const int t = tid & 255;
    const int mb = t << 2;            // m-vec base
    const int dp = mb >> PSH;
    const int ur = mb & ((1 << PSH) - 1);
    const int inb = (dp << (PSH + 2)) + ur;

    const int si = (SWZI == 1) ? (dp & 3) : (SWZI == 2) ? ((dp >> 1) & 3) : 0;
    const int so = (SWZO == 1) ? (((mb >> 6) & 3) << 4)
                 : (SWZO == 2) ? (((mb >> 5) & 3) << 2) : 0;

    u64 acc[8][2];
#pragma unroll
    for (int n = 0; n < 8; ++n) { acc[n][0] = 0ull; acc[n][1] = 0ull; }

#pragma unroll
    for (int k = 0; k < K; ++k) {
        const int off = (k >> 2) * 4096 + (((k & 3) ^ si) << PSH);
        const ulonglong2 xv = *(const ulonglong2*)(W + inb + off);
        const float4 alo = *(const float4*)(A + k * 16 + g * 8);
        const float4 ahi = *(const float4*)(A + k * 16 + g * 8 + 4);
        const float av[8] = { alo.x, alo.y, alo.z, alo.w,
                              ahi.x, ahi.y, ahi.z, ahi.w };
#pragma unroll
        for (int n = 0; n < 8; ++n) {
            const u64 a2 = pk(av[n]);
            fma2(acc[n][0], xv.x, a2);
            fma2(acc[n][1], xv.y, a2);
        }
    }

    __syncthreads();
#pragma unroll
    for (int n = 0; n < 8; ++n) {
        ulonglong2 o;
        o.x = acc[n][0];
        o.y = acc[n][1];
        *(ulonglong2*)(W + (((g * 8 + n) * 1024 + mb) ^ so)) = o;
    }
    __syncthreads();
}

// Interior step 5: F=1024, N=4, K=16 (layout rin*4096 + m*4 + u).
// m = t, t+512: conflict-free coalesced x loads (R10 fix).
__device__ __forceinline__ void step_fast_last(
    float* __restrict__ W, const float* __restrict__ A, int tid)
{
    const int m0 = tid;
    const int m1 = tid + 512;
    u64 acc[2][2];
    acc[0][0] = acc[0][1] = acc[1][0] = acc[1][1] = 0ull;

#pragma unroll
    for (int rin = 0; rin < 4; ++rin) {
        const float4 xv0 = *(const float4*)(W + m0 * 4 + rin * 4096);
        const float4 xv1 = *(const float4*)(W + m1 * 4 + rin * 4096);
#pragma unroll
        for (int u = 0; u < 4; ++u) {
            const float x0 = (u == 0) ? xv0.x : (u == 1) ? xv0.y : (u == 2) ? xv0.z : xv0.w;
            const float x1 = (u == 0) ? xv1.x : (u == 1) ? xv1.y : (u == 2) ? xv1.z : xv1.w;
            const ulonglong2 a2 = *(const ulonglong2*)(A + (rin * 4 + u) * 4);
            const u64 p0 = pk(x0);
            const u64 p1 = pk(x1);
            fma2(acc[0][0], p0, a2.x);
            fma2(acc[0][1], p0, a2.y);
            fma2(acc[1][0], p1, a2.x);
            fma2(acc[1][1], p1, a2.y);
        }
    }
    __syncthreads();
#pragma unroll
    for (int p = 0; p < 2; ++p) {
        const int m = (p == 0) ? m0 : m1;
        const float2 v01 = upk(acc[p][0]);
        const float2 v23 = upk(acc[p][1]);
        W[0 * 1024 + m] = v01.x;
        W[1 * 1024 + m] = v01.y;
        W[2 * 1024 + m] = v23.x;
        W[3 * 1024 + m] = v23.y;
    }
    __syncthreads();
}

__global__ __launch_bounds__(NT, 2)
void peps_half_kernel(const int* __restrict__ x, const float* __restrict__ T,
                      float* __restrict__ out)
{
    extern __shared__ float smem[];
    float* W = smem;                               // 16384
    float* As = smem + 16384;                      // 18 * 256 = 4608
    int* spins = (int*)(smem + 16384 + 4608);      // 36 (+ pad)

    const int blk = blockIdx.x;
    const bool top = blk < 1024;                   // ALL tops first, then bottoms
    const int b = top ? blk : (blk - 1024);
    const int tid = threadIdx.x;

    if (tid < 36) spins[tid] = x[b * 36 + tid];
    if (tid == 0) W[0] = 1.0f;
    __syncthreads();

    // Stage this half's 18 site matrices. Processed rows r'=0,1,2 map to
    // global rows gi = r' (top) or 5-r' (bottom); bottom swaps u/d strides
    // (vertical mirror). Direction sequence (L2R,R2L,L2R) identical -> the
    // final 4096-state layouts match bit-for-bit (verified in R9).
    const int ustr = top ? 64 : 4;
    const int dstr = top ? 4 : 64;
    for (int c = tid; c < 18 * 8; c += NT) {
        const int sidx = c >> 3;
        const int chunk = c & 7;
        const int r = sidx / 6;
        const int st = sidx - r * 6;
        const int gi = top ? r : (5 - r);
        const int ud = (r == 0) ? 1 : 4;
        const int dd = 4;
        const bool l2r = ((r & 1) == 0);
        const int Rin  = (st == 0) ? 1 : 4;
        const int Rout = (st == 5) ? 1 : 4;
        const int K = ud * Rin;
        const int N = Rout * dd;
        const int jc = l2r ? st : (5 - st);
        const int s = spins[gi * 6 + jc];
        const float* Tb = T + (size_t)((gi * 6 + jc) * 2 + s) * 256;
        const int kn = K * N;
        for (int idx = chunk * 32; idx < min(kn, chunk * 32 + 32); ++idx) {
            int k = idx / N, n = idx - k * N;
            int rin = k / ud, u = k - rin * ud;
            int rout = n / dd, d = n - rout * dd;
            int rr = l2r ? rout : rin;
            int ll = l2r ? rin : rout;
            As[sidx * 256 + idx] = Tb[u * ustr + rr * 16 + d * dstr + ll];
        }
    }
    __syncthreads();

    // ---- Processed row 0 (ud=1, dd=4, L2R) ----
    {
        const float* A = As;
        step_b<1,    1, 16, 1, 1, 1   >(W, A + 0 * 256, tid);
        step_b<4,    4, 16, 1, 1, 4   >(W, A + 1 * 256, tid);
        step_b<16,   4, 16, 1, 1, 16  >(W, A + 2 * 256, tid);
        step_b<64,   4, 16, 1, 1, 64  >(W, A + 3 * 256, tid);
        step_b<256,  4, 16, 1, 1, 256 >(W, A + 4 * 256, tid);
        step_b<1024, 4, 4,  1, 1, 1024>(W, A + 5 * 256, tid);
    }

    // ---- Processed rows 1,2 (interior, swizzled) ----
    for (int r = 1; r <= 2; ++r) {
        const float* A = As + r * 6 * 256;
        step_fast_vec<4, 10, 0, 0>(W, A + 0 * 256, tid);
        step_fast_vec<16, 8, 0, 0>(W, A + 1 * 256, tid);
        step_fast_vec<16, 6, 0, 1>(W, A + 2 * 256, tid);   // out: swz1
        step_fast_vec<16, 4, 1, 2>(W, A + 3 * 256, tid);   // in: swz1, out: swz2
        step_fast_vec<16, 2, 2, 0>(W, A + 4 * 256, tid);   // in: swz2
        step_fast_last(W, A + 5 * 256, tid);
    }
    // W holds the 4096-float boundary vector at the row2|row3 cut (unswizzled).

    if (top) {
        float* dst = g_vtop + (size_t)b * 4096;
        for (int i4 = tid; i4 < 1024; i4 += NT)
            ((float4*)dst)[i4] = ((const float4*)W)[i4];
        __syncthreads();                 // all V stores issued block-wide
        if (tid == 0) {
            asm volatile("st.release.gpu.global.u32 [%0], %1;"
                         :: "l"(&g_flag[b]), "r"(1u) : "memory");
        }
    } else {
        // Top was dispatched >= 1024 blocks earlier -> normally already done.
        if (tid == 0) {
            unsigned v;
            do {
                asm volatile("ld.acquire.gpu.global.u32 %0, [%1];"
                             : "=r"(v) : "l"(&g_flag[b]) : "memory");
                if (!v) __nanosleep(128);
            } while (!v);
        }
        __syncthreads();

        const float* src = g_vtop + (size_t)b * 4096;
        float p = 0.f;
        for (int i4 = tid; i4 < 1024; i4 += NT) {
            const float4 a = ((const float4*)src)[i4];
            const float4 w = ((const float4*)W)[i4];
            p += a.x * w.x + a.y * w.y + a.z * w.z + a.w * w.w;
        }
#pragma unroll
        for (int o = 16; o; o >>= 1)
            p += __shfl_down_sync(0xFFFFFFFFu, p, o);
        if ((tid & 31) == 0) As[tid >> 5] = p;   // reuse As as scratch
        __syncthreads();
        if (tid == 0) {
            float s = 0.f;
            for (int w = 0; w < NT / 32; ++w) s += As[w];
            out[b] = s;
            // Self-reset for the next graph replay (ordered by kernel boundary).
            asm volatile("st.relaxed.gpu.global.u32 [%0], %1;"
                         :: "l"(&g_flag[b]), "r"(0u) : "memory");
        }
    }
}

extern "C" void kernel_launch(void* const* d_in, const int* in_sizes, int n_in,
                              void* d_out, int out_size)
{
    const int T_ELEMS = 6 * 6 * 2 * 4 * 4 * 4 * 4;   // 73728
    const int* x;
    const float* T;
    if (in_sizes[0] == T_ELEMS) {
        T = (const float*)d_in[0];
        x = (const int*)d_in[1];
    } else {
        x = (const int*)d_in[0];
        T = (const float*)d_in[1];
    }

    const int smem_bytes = (16384 + 4608 + 64) * (int)sizeof(float);
    cudaFuncSetAttribute(peps_half_kernel,
                         cudaFuncAttributeMaxDynamicSharedMemorySize, smem_bytes);
    cudaFuncSetAttribute(peps_half_kernel,
                         cudaFuncAttributePreferredSharedMemoryCarveout, 100);

    peps_half_kernel<<<2 * out_size, NT, smem_bytes>>>(x, T, (float*)d_out);
}

// round 16
// speedup vs baseline: 1.0337x; 1.0337x over previous
#include <cuda_runtime.h>
#include <cuda_bf16.h>

// PEPS 6x6, D=4, phys=2, batch=1024. Row-sweep exact contraction, snake order.
// One CTA (512 threads) per config, single W buffer, 2 CTAs/SM.
// R14 interior engine (swizzled fma.rn.f32x2 m4n8). New in R16:
//  - staging uses shift arithmetic only (no runtime-divisor IDIV chains)
//  - row0 st4/st5 and row5 st0 vectorized (float4 + f32x2)
//  - row0 st0-st2 fused into one direct 256-thread step (saves 5 barriers)
//  - row5 st4+st5 fused into a warp-shuffle reduction (saves 3 barriers)

#define NT 512

typedef unsigned long long u64;

__device__ __forceinline__ u64 pk(float v) {
    u64 r;
    asm("mov.b64 %0, {%1, %1};" : "=l"(r) : "f"(v));
    return r;
}
__device__ __forceinline__ void fma2(u64& d, u64 a, u64 b) {
    asm("fma.rn.f32x2 %0, %1, %2, %0;" : "+l"(d) : "l"(a), "l"(b));
}
__device__ __forceinline__ float2 upk(u64 v) {
    float2 r;
    asm("mov.b64 {%0, %1}, %2;" : "=f"(r.x), "=f"(r.y) : "l"(v));
    return r;
}

// Scalar boundary step, compile-time shapes.
template <int F, int K, int N, int PU, int UD, int SRIN>
__device__ __forceinline__ void step_b(
    float* __restrict__ W, const float* __restrict__ A, int tid)
{
    constexpr int TOTAL = N * F;
    constexpr int NOUT = (TOTAL + NT - 1) / NT;
    float accl[NOUT];
    int cnt = 0;
    for (int o = tid; o < TOTAL; o += NT) {
        const int n = o / F;
        const int m = o - n * F;
        const int dp = m / PU;
        const int ur = m - dp * PU;
        const int inb = dp * UD * PU + ur;
        float s = 0.f;
#pragma unroll
        for (int k = 0; k < K; ++k) {
            const int rin = k / UD;
            const int u = k - rin * UD;
            s = fmaf(W[inb + rin * SRIN + u * PU], A[k * N + n], s);
        }
        accl[cnt++] = s;
    }
    __syncthreads();
    cnt = 0;
    for (int o = tid; o < TOTAL; o += NT) {
        const int n = o / F;
        const int m = o - n * F;
        W[n * F + m] = accl[cnt++];
    }
    __syncthreads();
}

// Vectorized boundary step for m-contiguous inputs (PU>=4 or PU==UD==1).
// Each thread: one float4 m-vec (2 m-pairs) x 2 n's. In-place two-phase.
template <int F, int K, int N, int PU, int UD, int SRIN>
__device__ __forceinline__ void step_bv(
    float* __restrict__ W, const float* __restrict__ A, int tid)
{
    constexpr int NV = F / 4;          // m-vecs
    constexpr int G = NT / NV;         // n-groups
    constexpr int NPG = N / G;         // n's per thread
    static_assert(NPG == 2, "step_bv expects 2 n per thread");
    const int g = tid / NV;
    const int tv = tid - g * NV;
    const int mb = tv * 4;
    const int dp = mb / PU;
    const int ur = mb - dp * PU;
    const int inb = dp * UD * PU + ur;
    const int n0 = g * NPG;

    u64 acc[2][2];                     // [n][m-pair]
    acc[0][0] = acc[0][1] = acc[1][0] = acc[1][1] = 0ull;

#pragma unroll
    for (int k = 0; k < K; ++k) {
        const int off = (k / UD) * SRIN + (k % UD) * PU;
        const ulonglong2 xv = *(const ulonglong2*)(W + inb + off);
        const u64 a0 = pk(A[k * N + n0]);
        const u64 a1 = pk(A[k * N + n0 + 1]);
        fma2(acc[0][0], xv.x, a0);
        fma2(acc[0][1], xv.y, a0);
        fma2(acc[1][0], xv.x, a1);
        fma2(acc[1][1], xv.y, a1);
    }
    __syncthreads();
#pragma unroll
    for (int n = 0; n < 2; ++n) {
        ulonglong2 o;
        o.x = acc[n][0];
        o.y = acc[n][1];
        *(ulonglong2*)(W + (n0 + n) * F + mb) = o;
    }
    __syncthreads();
}

// Interior steps 0..4: F=1024, N=16, Pu = 1<<PSH >= 4. XOR bank swizzles:
//   1: idx ^ (((idx>>6)&3)<<4)    2: idx ^ (((idx>>5)&3)<<2)
template <int K, int PSH, int SWZI, int SWZO>
__device__ __forceinline__ void step_fast_vec(
    float* __restrict__ W, const float* __restrict__ A, int tid)
{
    const int g = tid >> 8;
    const int t = tid & 255;
    const int mb = t << 2;
    const int dp = mb >> PSH;
    const int ur = mb & ((1 << PSH) - 1);
    const int inb = (dp << (PSH + 2)) + ur;

    const int si = (SWZI == 1) ? (dp & 3) : (SWZI == 2) ? ((dp >> 1) & 3) : 0;
    const int so = (SWZO == 1) ? (((mb >> 6) & 3) << 4)
                 : (SWZO == 2) ? (((mb >> 5) & 3) << 2) : 0;

    u64 acc[8][2];
#pragma unroll
    for (int n = 0; n < 8; ++n) { acc[n][0] = 0ull; acc[n][1] = 0ull; }

#pragma unroll
    for (int k = 0; k < K; ++k) {
        const int off = (k >> 2) * 4096 + (((k & 3) ^ si) << PSH);
        const ulonglong2 xv = *(const ulonglong2*)(W + inb + off);
        const float4 alo = *(const float4*)(A + k * 16 + g * 8);
        const float4 ahi = *(const float4*)(A + k * 16 + g * 8 + 4);
        const float av[8] = { alo.x, alo.y, alo.z, alo.w,
                              ahi.x, ahi.y, ahi.z, ahi.w };
#pragma unroll
        for (int n = 0; n < 8; ++n) {
            const u64 a2 = pk(av[n]);
            fma2(acc[n][0], xv.x, a2);
            fma2(acc[n][1], xv.y, a2);
        }
    }

    __syncthreads();
#pragma unroll
    for (int n = 0; n < 8; ++n) {
        ulonglong2 o;
        o.x = acc[n][0];
        o.y = acc[n][1];
        *(ulonglong2*)(W + (((g * 8 + n) * 1024 + mb) ^ so)) = o;
    }
    __syncthreads();
}

// Interior step 5: F=1024, N=4, K=16 (layout rin*4096 + m*4 + u).
__device__ __forceinline__ void step_fast_last(
    float* __restrict__ W, const float* __restrict__ A, int tid)
{
    const int m0 = tid;
    const int m1 = tid + 512;
    u64 acc[2][2];
    acc[0][0] = acc[0][1] = acc[1][0] = acc[1][1] = 0ull;

#pragma unroll
    for (int rin = 0; rin < 4; ++rin) {
        const float4 xv0 = *(const float4*)(W + m0 * 4 + rin * 4096);
        const float4 xv1 = *(const float4*)(W + m1 * 4 + rin * 4096);
#pragma unroll
        for (int u = 0; u < 4; ++u) {
            const float x0 = (u == 0) ? xv0.x : (u == 1) ? xv0.y : (u == 2) ? xv0.z : xv0.w;
            const float x1 = (u == 0) ? xv1.x : (u == 1) ? xv1.y : (u == 2) ? xv1.z : xv1.w;
            const ulonglong2 a2 = *(const ulonglong2*)(A + (rin * 4 + u) * 4);
            const u64 p0 = pk(x0);
            const u64 p1 = pk(x1);
            fma2(acc[0][0], p0, a2.x);
            fma2(acc[0][1], p0, a2.y);
            fma2(acc[1][0], p1, a2.x);
            fma2(acc[1][1], p1, a2.y);
        }
    }
    __syncthreads();
#pragma unroll
    for (int p = 0; p < 2; ++p) {
        const int m = (p == 0) ? m0 : m1;
        const float2 v01 = upk(acc[p][0]);
        const float2 v23 = upk(acc[p][1]);
        W[0 * 1024 + m] = v01.x;
        W[1 * 1024 + m] = v01.y;
        W[2 * 1024 + m] = v23.x;
        W[3 * 1024 + m] = v23.y;
    }
    __syncthreads();
}

__global__ __launch_bounds__(NT, 2)
void peps_amp_kernel(const int* __restrict__ x, const float* __restrict__ T,
                     float* __restrict__ out)
{
    extern __shared__ float smem[];
    float* W = smem;                               // [0, 16384)
    float* As = smem + 16384;                      // 36 * 256 = 9216 floats
    int* spins = (int*)(smem + 16384 + 9216);      // 36 (+ pad)

    const int b = blockIdx.x;
    const int tid = threadIdx.x;

    if (tid < 36) spins[tid] = x[b * 36 + tid];
    __syncthreads();

    // Stage ALL 36 site matrices: As[(i*6+st)*256 + k*N + n],
    // k = rin*ud + u, n = rout*dd + d. All divisors are powers of 2 -> shifts.
    for (int site = tid; site < 36 * 8; site += NT) {
        const int sidx = site >> 3;
        const int chunk = site & 7;
        const int i = sidx / 6;                    // constant divisor: cheap
        const int st = sidx - i * 6;
        const int udsh = (i == 0) ? 0 : 2;
        const int ddsh = (i == 5) ? 0 : 2;
        const int rish = (st == 0) ? 0 : 2;        // log2(Rin)
        const int rosh = (st == 5) ? 0 : 2;        // log2(Rout)
        const int nsh = rosh + ddsh;               // log2(N)
        const int kn = 1 << (udsh + rish + nsh);   // K*N
        const bool l2r = ((i & 1) == 0);
        const int jc = l2r ? st : (5 - st);
        const int s = spins[i * 6 + jc];
        const float* Tb = T + (size_t)((i * 6 + jc) * 2 + s) * 256;
        const int hi = min(kn, chunk * 32 + 32);
        for (int idx = chunk * 32; idx < hi; ++idx) {
            const int k = idx >> nsh;
            const int n = idx & ((1 << nsh) - 1);
            const int rin = k >> udsh;
            const int u = k & ((1 << udsh) - 1);
            const int rout = n >> ddsh;
            const int d = n & ((1 << ddsh) - 1);
            const int r = l2r ? rout : rin;
            const int l = l2r ? rin : rout;
            As[sidx * 256 + idx] = Tb[u * 64 + r * 16 + d * 4 + l];
        }
    }
    __syncthreads();

    // ---- Row 0 head: st0..st2 fused (direct evaluation of 256 outputs) ----
    // W[(r2,d2)*16 + d1*4 + d0] =
    //   sum_{r1} ( sum_{r0} A0[r0*4+d0] * A1[r0*16+r1*4+d1] ) * A2[r1*16+(r2,d2)]
    {
        const float* A0 = As;
        const float* A1 = As + 256;
        const float* A2 = As + 512;
        if (tid < 256) {
            const int d0 = tid & 3;
            const int d1 = (tid >> 2) & 3;
            const int n2 = tid >> 4;               // (r2,d2)
            float s = 0.f;
#pragma unroll
            for (int r1 = 0; r1 < 4; ++r1) {
                float t1 = 0.f;
#pragma unroll
                for (int r0 = 0; r0 < 4; ++r0)
                    t1 = fmaf(A0[r0 * 4 + d0], A1[r0 * 16 + r1 * 4 + d1], t1);
                s = fmaf(t1, A2[r1 * 16 + n2], s);
            }
            W[tid] = s;
        }
        __syncthreads();
    }
    // ---- Row 0 st3..st5 ----
    step_b <64,   4, 16, 1, 1, 64  >(W, As + 3 * 256, tid);
    step_bv<256,  4, 16, 1, 1, 256 >(W, As + 4 * 256, tid);
    step_bv<1024, 4, 4,  1, 1, 1024>(W, As + 5 * 256, tid);

    // ---- Rows 1..4 (interior, swizzled) ----
    for (int i = 1; i <= 4; ++i) {
        const float* A = As + i * 6 * 256;
        step_fast_vec<4, 10, 0, 0>(W, A + 0 * 256, tid);
        step_fast_vec<16, 8, 0, 0>(W, A + 1 * 256, tid);
        step_fast_vec<16, 6, 0, 1>(W, A + 2 * 256, tid);   // out: swz1
        step_fast_vec<16, 4, 1, 2>(W, A + 3 * 256, tid);   // in: swz1, out: swz2
        step_fast_vec<16, 2, 2, 0>(W, A + 4 * 256, tid);   // in: swz2
        step_fast_last(W, A + 5 * 256, tid);
    }

    // ---- Row 5 (ud=4, dd=1, R->L) ----
    {
        const float* A = As + 5 * 6 * 256;
        step_bv<1024, 4,  4, 1024, 4, 4096>(W, A + 0 * 256, tid);
        step_b<256, 16,  4, 256,  4, 1024>(W, A + 1 * 256, tid);
        step_b<64,  16,  4, 64,   4, 256 >(W, A + 2 * 256, tid);
        step_b<16,  16,  4, 16,   4, 64  >(W, A + 3 * 256, tid);
        // st4 + st5 fused: 16 threads compute st4's outputs, then warp-reduce
        // against A5 (st5's x-index (rin,u) == st4's output index (n,m)).
        if (tid < 32) {
            const float* A4 = A + 4 * 256;
            const float* A5 = A + 5 * 256;
            float v = 0.f;
            if (tid < 16) {
                const int n = tid >> 2;
                const int m = tid & 3;
                float s = 0.f;
#pragma unroll
                for (int k = 0; k < 16; ++k)
                    s = fmaf(W[m + (k >> 2) * 16 + (k & 3) * 4], A4[k * 4 + n], s);
                v = s * A5[tid];
            }
#pragma unroll
            for (int o = 8; o; o >>= 1)
                v += __shfl_down_sync(0xFFFFFFFFu, v, o);
            if (tid == 0) out[b] = v;
        }
    }
}

extern "C" void kernel_launch(void* const* d_in, const int* in_sizes, int n_in,
                              void* d_out, int out_size)
{
    const int T_ELEMS = 6 * 6 * 2 * 4 * 4 * 4 * 4;   // 73728
    const int* x;
    const float* T;
    if (in_sizes[0] == T_ELEMS) {
        T = (const float*)d_in[0];
        x = (const int*)d_in[1];
    } else {
        x = (const int*)d_in[0];
        T = (const float*)d_in[1];
    }

    const int smem_bytes = (16384 + 9216 + 64) * (int)sizeof(float);
    cudaFuncSetAttribute(peps_amp_kernel,
                         cudaFuncAttributeMaxDynamicSharedMemorySize, smem_bytes);
    cudaFuncSetAttribute(peps_amp_kernel,
                         cudaFuncAttributePreferredSharedMemoryCarveout, 100);

    peps_amp_kernel<<<out_size, NT, smem_bytes>>>(x, T, (float*)d_out);
}